// round 1
// baseline (speedup 1.0000x reference)
#include <cuda_runtime.h>
#include <math.h>

#define N_PTS   524288
#define GRID_R  300
#define NCOMP   36
#define SDF_DIM 256
#define IN_CH   129      // 21 embed + 108 feats
#define OUT_CH  129
#define NWARPS  16
#define THREADS (NWARPS*32)
#define H_STRIDE 264     // h_s row stride (16B aligned: 264*4=1056)
#define IN_STRIDE 132

// ---- static device scratch (no runtime allocation) ----
__device__ float g_planesT[3*GRID_R*GRID_R*NCOMP];  // [p][y][x][c]  ~38.9MB
__device__ float g_linesT [3*GRID_R*NCOMP];         // [p][z][c]
__device__ float g_w1T    [IN_CH*SDF_DIM];          // [i][j]  (w1 is [256][129])
__device__ float g_w2T    [SDF_DIM*128];            // [j][c]  cols 0..127 (w2 is [129][256])

// ---------------- pre-pass kernels ----------------
__global__ void transpose_planes_kernel(const float* __restrict__ planes) {
    int idx = blockIdx.x*blockDim.x + threadIdx.x;
    const int total = 3*GRID_R*GRID_R*NCOMP;
    if (idx >= total) return;
    int c = idx % NCOMP;
    int t = idx / NCOMP;
    int x = t % GRID_R; t /= GRID_R;
    int y = t % GRID_R;
    int p = t / GRID_R;
    g_planesT[idx] = planes[((p*NCOMP + c)*GRID_R + y)*GRID_R + x];
}

__global__ void prep_small_kernel(const float* __restrict__ lines,
                                  const float* __restrict__ w1,
                                  const float* __restrict__ w2) {
    int idx = blockIdx.x*blockDim.x + threadIdx.x;
    if (idx < 3*GRID_R*NCOMP) {
        int c = idx % NCOMP;
        int t = idx / NCOMP;
        int z = t % GRID_R;
        int p = t / GRID_R;
        g_linesT[idx] = lines[(p*NCOMP + c)*GRID_R + z];
    }
    if (idx < IN_CH*SDF_DIM) {
        int j = idx % SDF_DIM;
        int i = idx / SDF_DIM;
        g_w1T[idx] = w1[j*IN_CH + i];
    }
    if (idx < SDF_DIM*128) {
        int c = idx % 128;
        int j = idx / 128;
        g_w2T[idx] = w2[c*SDF_DIM + j];
    }
}

// ---------------- main fused kernel ----------------
__global__ __launch_bounds__(THREADS, 1)
void tensosdf_main(const float* __restrict__ xyz,
                   const float* __restrict__ w2,   // original [129][256] for col 128
                   const float* __restrict__ b1,
                   const float* __restrict__ b2,
                   float* __restrict__ out)
{
    extern __shared__ float smem[];
    float* w1s  = smem;                                   // 129*256
    float* in_s = w1s + IN_CH*SDF_DIM;                    // NWARPS*IN_STRIDE
    float* h_s  = in_s + NWARPS*IN_STRIDE;                // NWARPS*H_STRIDE

    const int tid  = threadIdx.x;
    const int w    = tid >> 5;
    const int lane = tid & 31;

    // load w1T into smem (coalesced)
    for (int i = tid; i < IN_CH*SDF_DIM; i += THREADS) w1s[i] = g_w1T[i];
    __syncthreads();

    float* my_in = in_s + w*IN_STRIDE;
    float* my_h  = h_s  + w*H_STRIDE;

    // per-lane constants
    float b1v[8];
    #pragma unroll
    for (int k = 0; k < 8; k++) b1v[k] = b1[8*lane + k];
    const float b2_128 = b2[128];

    // cooperative layer-2 lane mapping: pt = lane&15, col quad = (lane>>4)
    const int l2_pt = lane & 15;
    const int l2_cq = lane >> 4;
    const int l2_col = 8*w + 4*l2_cq;                     // cols 8w..8w+7 per warp
    float b2q[4];
    #pragma unroll
    for (int k = 0; k < 4; k++) b2q[k] = b2[l2_col + k];

    const int stride_pts = gridDim.x * NWARPS;

    for (int base = blockIdx.x * NWARPS; base < N_PTS; base += stride_pts) {
        const int pt = base + w;   // this warp's point (always valid: N_PTS % 16 == 0)

        // ---- gather + embed (warp-local) ----
        const float x0 = xyz[pt*3 + 0];
        const float x1 = xyz[pt*3 + 1];
        const float x2 = xyz[pt*3 + 2];

        if (lane < 21) {
            float v;
            if (lane < 3) {
                v = (lane == 0) ? x0 : ((lane == 1) ? x1 : x2);
            } else {
                int t = lane - 3;
                int iscos = (t >= 9);
                int tt = iscos ? t - 9 : t;
                int dim = tt / 3, fr = tt % 3;
                float xv = (dim == 0) ? x0 : ((dim == 1) ? x1 : x2);
                float ang = xv * (float)(1 << fr);
                v = iscos ? __cosf(ang) : __sinf(ang);
            }
            my_in[lane] = v;
        }

        #pragma unroll
        for (int p = 0; p < 3; p++) {
            float px = (p == 2) ? x1 : x0;
            float py = (p == 0) ? x1 : x2;
            float pz = (p == 0) ? x2 : ((p == 1) ? x1 : x0);
            float fx = (px + 1.f) * 0.5f * (GRID_R - 1);
            float fy = (py + 1.f) * 0.5f * (GRID_R - 1);
            float fz = (pz + 1.f) * 0.5f * (GRID_R - 1);
            int ix = min(max((int)floorf(fx), 0), GRID_R - 2);
            int iy = min(max((int)floorf(fy), 0), GRID_R - 2);
            int iz = min(max((int)floorf(fz), 0), GRID_R - 2);
            float tx = fx - (float)ix, ty = fy - (float)iy, tz = fz - (float)iz;
            const float* pb = g_planesT + ((size_t)(p*GRID_R + iy)*GRID_R + ix)*NCOMP;
            const float* lb = g_linesT  + (size_t)(p*GRID_R + iz)*NCOMP;
            float w00 = (1.f - tx) * (1.f - ty);
            float w01 = tx * (1.f - ty);
            float w10 = (1.f - tx) * ty;
            float w11 = tx * ty;
            #pragma unroll
            for (int ci = 0; ci < 2; ci++) {
                int c = ci*32 + lane;
                if (c < NCOMP) {
                    float v00 = pb[c];
                    float v01 = pb[NCOMP + c];
                    float v10 = pb[GRID_R*NCOMP + c];
                    float v11 = pb[GRID_R*NCOMP + NCOMP + c];
                    float pv = v00*w00 + v01*w01 + v10*w10 + v11*w11;
                    float l0 = lb[c], l1 = lb[NCOMP + c];
                    float lv = l0 + tz * (l1 - l0);
                    my_in[21 + p*36 + c] = pv * lv;
                }
            }
        }
        __syncwarp();

        // ---- layer 1: lane owns hidden units 8*lane .. 8*lane+7 ----
        float acc[8];
        #pragma unroll
        for (int k = 0; k < 8; k++) acc[k] = b1v[k];

        #pragma unroll 4
        for (int i = 0; i < IN_CH; i++) {
            float v = my_in[i];
            const float4 wa = *(const float4*)(w1s + i*SDF_DIM + 8*lane);
            const float4 wb = *(const float4*)(w1s + i*SDF_DIM + 8*lane + 4);
            acc[0] = fmaf(v, wa.x, acc[0]);
            acc[1] = fmaf(v, wa.y, acc[1]);
            acc[2] = fmaf(v, wa.z, acc[2]);
            acc[3] = fmaf(v, wa.w, acc[3]);
            acc[4] = fmaf(v, wb.x, acc[4]);
            acc[5] = fmaf(v, wb.y, acc[5]);
            acc[6] = fmaf(v, wb.z, acc[6]);
            acc[7] = fmaf(v, wb.w, acc[7]);
        }

        // stable softplus(100 t)/100
        #pragma unroll
        for (int k = 0; k < 8; k++) {
            float t = acc[k];
            acc[k] = fmaxf(t, 0.f) + 0.01f * log1pf(__expf(-fabsf(100.f * t)));
        }

        // publish h (guard against prior-iteration layer-2 readers)
        __syncthreads();
        *(float4*)(my_h + 8*lane)     = make_float4(acc[0], acc[1], acc[2], acc[3]);
        *(float4*)(my_h + 8*lane + 4) = make_float4(acc[4], acc[5], acc[6], acc[7]);
        __syncthreads();

        // ---- layer 2 (block-cooperative): warp w does cols 8w..8w+7 for all 16 pts ----
        float o0 = 0.f, o1 = 0.f, o2 = 0.f, o3 = 0.f;
        const float* hrow = h_s + l2_pt * H_STRIDE;
        #pragma unroll 4
        for (int j = 0; j < SDF_DIM; j++) {
            float hj = hrow[j];
            const float4 wv = *(const float4*)(g_w2T + j*128 + l2_col);
            o0 = fmaf(hj, wv.x, o0);
            o1 = fmaf(hj, wv.y, o1);
            o2 = fmaf(hj, wv.z, o2);
            o3 = fmaf(hj, wv.w, o3);
        }
        {
            float* op = out + (size_t)(base + l2_pt) * OUT_CH + l2_col;
            op[0] = o0 + b2q[0];
            op[1] = o1 + b2q[1];
            op[2] = o2 + b2q[2];
            op[3] = o3 + b2q[3];
        }

        // ---- col 128: warp w handles its own point via warp reduction ----
        float p128 = 0.f;
        #pragma unroll
        for (int m = 0; m < 8; m++) {
            int j = lane + 32*m;
            p128 = fmaf(my_h[j], w2[128*SDF_DIM + j], p128);
        }
        #pragma unroll
        for (int off = 16; off; off >>= 1)
            p128 += __shfl_xor_sync(0xffffffffu, p128, off);
        if (lane == 0)
            out[(size_t)pt * OUT_CH + 128] = p128 + b2_128;
    }
}

// ---------------- launch ----------------
extern "C" void kernel_launch(void* const* d_in, const int* in_sizes, int n_in,
                              void* d_out, int out_size) {
    const float* xyz    = (const float*)d_in[0];
    const float* planes = (const float*)d_in[1];
    const float* lines  = (const float*)d_in[2];
    const float* w1     = (const float*)d_in[3];
    const float* b1     = (const float*)d_in[4];
    const float* w2     = (const float*)d_in[5];
    const float* b2     = (const float*)d_in[6];
    float* out = (float*)d_out;

    int sms = 148;
    cudaDeviceGetAttribute(&sms, cudaDevAttrMultiProcessorCount, 0);

    const int ptot = 3*GRID_R*GRID_R*NCOMP;
    transpose_planes_kernel<<<(ptot + 255)/256, 256>>>(planes);
    prep_small_kernel<<<(IN_CH*SDF_DIM + 255)/256, 256>>>(lines, w1, w2);

    const int smem_bytes = (IN_CH*SDF_DIM + NWARPS*IN_STRIDE + NWARPS*H_STRIDE) * (int)sizeof(float);
    cudaFuncSetAttribute(tensosdf_main, cudaFuncAttributeMaxDynamicSharedMemorySize, smem_bytes);

    int blocks = sms * 8;
    tensosdf_main<<<blocks, THREADS, smem_bytes>>>(xyz, w2, b1, b2, out);
}

// round 2
// speedup vs baseline: 3.2570x; 3.2570x over previous
#include <cuda_runtime.h>
#include <math.h>

#define N_PTS   524288
#define GRID_R  300
#define NCOMP   36
#define SDF_DIM 256
#define IN_CH   129      // 21 embed + 108 feats
#define OUT_CH  129
#define NWARPS  16
#define THREADS (NWARPS*32)
#define PPW     4                 // points per warp (layer 1)
#define PTS_PER_TILE (NWARPS*PPW) // 64
#define BUF_STRIDE 259            // odd: 3*pt mod 32 distinct -> conflict-free h reads
#define N_TILES (N_PTS/PTS_PER_TILE)

typedef unsigned long long u64;

// ---- static device scratch ----
__device__ float g_planesT[3*GRID_R*GRID_R*NCOMP];  // [p][y][x][c]
__device__ float g_linesT [3*GRID_R*NCOMP];         // [p][z][c]
__device__ float g_w1T    [IN_CH*SDF_DIM];          // [i][j]
__device__ float g_w2T    [SDF_DIM*128];            // [j][c] cols 0..127

// ---- packed f32x2 helpers ----
__device__ __forceinline__ void ffma2(u64 &d, u64 a, u64 b) {
    asm("fma.rn.f32x2 %0, %1, %2, %0;" : "+l"(d) : "l"(a), "l"(b));
}
__device__ __forceinline__ u64 pack2(float lo, float hi) {
    u64 r; asm("mov.b64 %0, {%1,%2};" : "=l"(r) : "f"(lo), "f"(hi)); return r;
}
__device__ __forceinline__ void unpack2(u64 v, float &lo, float &hi) {
    asm("mov.b64 {%0,%1}, %2;" : "=f"(lo), "=f"(hi) : "l"(v));
}

// ---------------- pre-pass kernels ----------------
__global__ void transpose_planes_kernel(const float* __restrict__ planes) {
    int idx = blockIdx.x*blockDim.x + threadIdx.x;
    const int total = 3*GRID_R*GRID_R*NCOMP;
    if (idx >= total) return;
    int c = idx % NCOMP;
    int t = idx / NCOMP;
    int x = t % GRID_R; t /= GRID_R;
    int y = t % GRID_R;
    int p = t / GRID_R;
    g_planesT[idx] = planes[((p*NCOMP + c)*GRID_R + y)*GRID_R + x];
}

__global__ void prep_small_kernel(const float* __restrict__ lines,
                                  const float* __restrict__ w1,
                                  const float* __restrict__ w2) {
    int idx = blockIdx.x*blockDim.x + threadIdx.x;
    if (idx < 3*GRID_R*NCOMP) {
        int c = idx % NCOMP;
        int t = idx / NCOMP;
        int z = t % GRID_R;
        int p = t / GRID_R;
        g_linesT[idx] = lines[(p*NCOMP + c)*GRID_R + z];
    }
    if (idx < IN_CH*SDF_DIM) {
        int j = idx % SDF_DIM;
        int i = idx / SDF_DIM;
        g_w1T[idx] = w1[j*IN_CH + i];
    }
    if (idx < SDF_DIM*128) {
        int c = idx % 128;
        int j = idx / 128;
        g_w2T[idx] = w2[c*SDF_DIM + j];
    }
}

// ---------------- main fused kernel ----------------
__global__ __launch_bounds__(THREADS, 1)
void tensosdf_main(const float* __restrict__ xyz,
                   const float* __restrict__ w2,   // original [129][256] (row 128)
                   const float* __restrict__ b1,
                   const float* __restrict__ b2,
                   float* __restrict__ out)
{
    extern __shared__ float smem[];
    float* w1s = smem;                                   // 129*256 floats
    float* buf = w1s + IN_CH*SDF_DIM;                    // 64 * BUF_STRIDE
    float* w2c = buf + PTS_PER_TILE*BUF_STRIDE;          // 32*128 chunk

    const int tid  = threadIdx.x;
    const int w    = tid >> 5;
    const int lane = tid & 31;

    // load w1T into smem (coalesced)
    for (int i = tid; i < IN_CH*SDF_DIM; i += THREADS) w1s[i] = g_w1T[i];

    const u64* w1s64 = (const u64*)w1s;

    // layer-1: lane owns unit pairs {2*lane + 64k, +1}, k=0..3  (8 units)
    u64 b1p[4];
    #pragma unroll
    for (int k = 0; k < 4; k++)
        b1p[k] = ((const u64*)b1)[lane + 32*k];

    // col-128 weights for this lane's units
    float w2r128[8];
    #pragma unroll
    for (int k = 0; k < 4; k++) {
        w2r128[2*k]   = w2[128*SDF_DIM + 2*lane + 64*k];
        w2r128[2*k+1] = w2[128*SDF_DIM + 2*lane + 64*k + 1];
    }
    const float b2_128 = b2[128];

    // layer-2: warp owns cols 8w..8w+7; preload b2 for those cols
    const int colb = 8*w;
    float b2r[8];
    #pragma unroll
    for (int k = 0; k < 8; k++) b2r[k] = b2[colb + k];

    float* bufw[PPW];
    #pragma unroll
    for (int t = 0; t < PPW; t++) bufw[t] = buf + (PPW*w + t)*BUF_STRIDE;

    for (int tile = blockIdx.x; tile < N_TILES; tile += gridDim.x) {
        const int base = tile * PTS_PER_TILE;
        __syncthreads();   // prev iteration's layer-2 reads of buf done

        // ================= gather + embed (warp-local, 4 points) =================
        #pragma unroll
        for (int t = 0; t < PPW; t++) {
            const int pt = base + PPW*w + t;
            float* my_in = bufw[t];
            const float x0 = xyz[pt*3 + 0];
            const float x1 = xyz[pt*3 + 1];
            const float x2 = xyz[pt*3 + 2];

            if (lane < 21) {
                float v;
                if (lane < 3) {
                    v = (lane == 0) ? x0 : ((lane == 1) ? x1 : x2);
                } else {
                    int tt = lane - 3;
                    int iscos = (tt >= 9);
                    int q = iscos ? tt - 9 : tt;
                    int dim = q / 3, fr = q % 3;
                    float xv = (dim == 0) ? x0 : ((dim == 1) ? x1 : x2);
                    float ang = xv * (float)(1 << fr);
                    v = iscos ? __cosf(ang) : __sinf(ang);
                }
                my_in[lane] = v;
            }

            #pragma unroll
            for (int p = 0; p < 3; p++) {
                float px = (p == 2) ? x1 : x0;
                float py = (p == 0) ? x1 : x2;
                float pz = (p == 0) ? x2 : ((p == 1) ? x1 : x0);
                float fx = (px + 1.f) * 0.5f * (GRID_R - 1);
                float fy = (py + 1.f) * 0.5f * (GRID_R - 1);
                float fz = (pz + 1.f) * 0.5f * (GRID_R - 1);
                int ix = min(max((int)floorf(fx), 0), GRID_R - 2);
                int iy = min(max((int)floorf(fy), 0), GRID_R - 2);
                int iz = min(max((int)floorf(fz), 0), GRID_R - 2);
                float tx = fx - (float)ix, ty = fy - (float)iy, tz = fz - (float)iz;
                const float* pb = g_planesT + ((size_t)(p*GRID_R + iy)*GRID_R + ix)*NCOMP;
                const float* lb = g_linesT  + (size_t)(p*GRID_R + iz)*NCOMP;
                float w00 = (1.f - tx) * (1.f - ty);
                float w01 = tx * (1.f - ty);
                float w10 = (1.f - tx) * ty;
                float w11 = tx * ty;
                #pragma unroll
                for (int ci = 0; ci < 2; ci++) {
                    int c = ci*32 + lane;
                    if (c < NCOMP) {
                        float v00 = pb[c];
                        float v01 = pb[NCOMP + c];
                        float v10 = pb[GRID_R*NCOMP + c];
                        float v11 = pb[GRID_R*NCOMP + NCOMP + c];
                        float pv = v00*w00 + v01*w01 + v10*w10 + v11*w11;
                        float l0 = lb[c], l1 = lb[NCOMP + c];
                        float lv = l0 + tz * (l1 - l0);
                        my_in[21 + p*36 + c] = pv * lv;
                    }
                }
            }
        }
        __syncwarp();

        // ================= layer 1: 4 points x 8 units, packed FFMA2 =================
        u64 acc[PPW][4];
        #pragma unroll
        for (int t = 0; t < PPW; t++)
            #pragma unroll
            for (int k = 0; k < 4; k++) acc[t][k] = b1p[k];

        #pragma unroll 3
        for (int i = 0; i < IN_CH; i++) {
            const u64 wl0 = w1s64[i*128 + lane];
            const u64 wl1 = w1s64[i*128 + lane + 32];
            const u64 wl2 = w1s64[i*128 + lane + 64];
            const u64 wl3 = w1s64[i*128 + lane + 96];
            #pragma unroll
            for (int t = 0; t < PPW; t++) {
                float v = bufw[t][i];
                u64 vv = pack2(v, v);
                ffma2(acc[t][0], vv, wl0);
                ffma2(acc[t][1], vv, wl1);
                ffma2(acc[t][2], vv, wl2);
                ffma2(acc[t][3], vv, wl3);
            }
        }

        // softplus, store h to buf, col-128 dot + reduce
        #pragma unroll
        for (int t = 0; t < PPW; t++) {
            float h[8];
            #pragma unroll
            for (int k = 0; k < 4; k++) {
                float a, b;
                unpack2(acc[t][k], a, b);
                h[2*k]   = fmaxf(a, 0.f) + 0.01f * __logf(1.f + __expf(-fabsf(100.f * a)));
                h[2*k+1] = fmaxf(b, 0.f) + 0.01f * __logf(1.f + __expf(-fabsf(100.f * b)));
            }
            float* hb = bufw[t];
            #pragma unroll
            for (int k = 0; k < 4; k++) {
                hb[2*lane + 64*k]     = h[2*k];
                hb[2*lane + 64*k + 1] = h[2*k+1];
            }
            float s = 0.f;
            #pragma unroll
            for (int m = 0; m < 8; m++) s = fmaf(h[m], w2r128[m], s);
            #pragma unroll
            for (int off = 16; off; off >>= 1)
                s += __shfl_xor_sync(0xffffffffu, s, off);
            if (lane == 0)
                out[(size_t)(base + PPW*w + t) * OUT_CH + 128] = s + b2_128;
        }

        // ================= layer 2: cols 8w..8w+7 for all 64 points =================
        u64 o0[4], o1[4];   // two point-tiles: pt = lane and pt = 32+lane
        #pragma unroll
        for (int k = 0; k < 4; k++) { o0[k] = 0ull; o1[k] = 0ull; }

        const float* h0b = buf + lane*BUF_STRIDE;
        const float* h1b = buf + (32 + lane)*BUF_STRIDE;

        for (int jc = 0; jc < 8; jc++) {
            __syncthreads();   // (first pass: also publishes h block-wide)
            {
                const float4* src = (const float4*)g_w2T + jc*1024;
                float4* dst = (float4*)w2c;
                dst[tid]       = src[tid];
                dst[tid + 512] = src[tid + 512];
            }
            __syncthreads();
            const ulonglong2* w2c128 = (const ulonglong2*)w2c;
            #pragma unroll 4
            for (int j = 0; j < 32; j++) {
                const int jj = jc*32 + j;
                ulonglong2 wa = w2c128[j*32 + 2*w];       // cols 8w..8w+3
                ulonglong2 wb = w2c128[j*32 + 2*w + 1];   // cols 8w+4..8w+7
                float hv0 = h0b[jj];
                float hv1 = h1b[jj];
                u64 hh0 = pack2(hv0, hv0);
                u64 hh1 = pack2(hv1, hv1);
                ffma2(o0[0], hh0, wa.x);
                ffma2(o0[1], hh0, wa.y);
                ffma2(o0[2], hh0, wb.x);
                ffma2(o0[3], hh0, wb.y);
                ffma2(o1[0], hh1, wa.x);
                ffma2(o1[1], hh1, wa.y);
                ffma2(o1[2], hh1, wb.x);
                ffma2(o1[3], hh1, wb.y);
            }
        }

        // epilogue: bias + store (8 cols x 2 points per lane)
        {
            float* op0 = out + (size_t)(base + lane) * OUT_CH + colb;
            float* op1 = out + (size_t)(base + 32 + lane) * OUT_CH + colb;
            #pragma unroll
            for (int k = 0; k < 4; k++) {
                float a, b;
                unpack2(o0[k], a, b);
                op0[2*k]   = a + b2r[2*k];
                op0[2*k+1] = b + b2r[2*k+1];
                unpack2(o1[k], a, b);
                op1[2*k]   = a + b2r[2*k];
                op1[2*k+1] = b + b2r[2*k+1];
            }
        }
    }
}

// ---------------- launch ----------------
extern "C" void kernel_launch(void* const* d_in, const int* in_sizes, int n_in,
                              void* d_out, int out_size) {
    const float* xyz    = (const float*)d_in[0];
    const float* planes = (const float*)d_in[1];
    const float* lines  = (const float*)d_in[2];
    const float* w1     = (const float*)d_in[3];
    const float* b1     = (const float*)d_in[4];
    const float* w2     = (const float*)d_in[5];
    const float* b2     = (const float*)d_in[6];
    float* out = (float*)d_out;

    int sms = 148;
    cudaDeviceGetAttribute(&sms, cudaDevAttrMultiProcessorCount, 0);

    const int ptot = 3*GRID_R*GRID_R*NCOMP;
    transpose_planes_kernel<<<(ptot + 255)/256, 256>>>(planes);
    prep_small_kernel<<<(IN_CH*SDF_DIM + 255)/256, 256>>>(lines, w1, w2);

    const int smem_bytes = (IN_CH*SDF_DIM + PTS_PER_TILE*BUF_STRIDE + 32*128) * (int)sizeof(float);
    cudaFuncSetAttribute(tensosdf_main, cudaFuncAttributeMaxDynamicSharedMemorySize, smem_bytes);

    tensosdf_main<<<sms, THREADS, smem_bytes>>>(xyz, w2, b1, b2, out);
}

// round 4
// speedup vs baseline: 10.0113x; 3.0737x over previous
#include <cuda_runtime.h>
#include <cuda_bf16.h>
#include <math.h>
#include <cstdint>

#define N_PTS   524288
#define GRID_R  300
#define NCOMP   36
#define SDF_DIM 256
#define IN_CH   129
#define OUT_CH  129
#define TILE_M  128
#define N_TILES (N_PTS / TILE_M)      // 4096
#define THREADS 256                   // 8 warps

// strides in bf16 elements (bytes = *2). Chosen so row-byte-stride/16 is odd
// -> conflict-free ldmatrix (304B and 528B).
#define XSTR 152     // X rows: k 0..143 used
#define HSTR 264     // H rows: k 0..255 used; also w2 smem stride

// smem offsets (bytes)
#define XH_OFF   0                    // X (38912) / H (67584) / stage (66560)
#define W1S_OFF  67584                // 256 x 304B = 77824
#define W2S_OFF  145408               // 128 x 528B = 67584
#define LUT_OFF  212992               // 256 * 8
#define W2C_OFF  215040               // 256 * 4
#define B2S_OFF  216064               // 132 * 4 = 528
#define C128A_OFF 216592              // 128 * 4
#define C128B_OFF 217104              // 128 * 4
#define SMEM_TOTAL 217728

typedef unsigned int u32;

__device__ float g_planesT[3*GRID_R*GRID_R*NCOMP];
__device__ float g_linesT [3*GRID_R*NCOMP];
__device__ __align__(16) unsigned short g_w1bf[256*144];   // [n][k], k129=b1, 130..143=0
__device__ __align__(16) unsigned short g_w2bf[128*256];   // [n][k]

__device__ __forceinline__ u32 smem_u32(const void* p) {
    u32 a; asm("{ .reg .u64 t; cvta.to.shared.u64 t, %1; cvt.u32.u64 %0, t; }" : "=r"(a) : "l"(p));
    return a;
}
__device__ __forceinline__ void ldsm4(u32* r, u32 addr) {
    asm volatile("ldmatrix.sync.aligned.m8n8.x4.shared.b16 {%0,%1,%2,%3}, [%4];"
        : "=r"(r[0]), "=r"(r[1]), "=r"(r[2]), "=r"(r[3]) : "r"(addr));
}
__device__ __forceinline__ void mma16816(float* c, const u32* a, u32 b0, u32 b1) {
    asm volatile("mma.sync.aligned.m16n8k16.row.col.f32.bf16.bf16.f32 "
        "{%0,%1,%2,%3}, {%4,%5,%6,%7}, {%8,%9}, {%0,%1,%2,%3};"
        : "+f"(c[0]), "+f"(c[1]), "+f"(c[2]), "+f"(c[3])
        : "r"(a[0]), "r"(a[1]), "r"(a[2]), "r"(a[3]), "r"(b0), "r"(b1));
}
__device__ __forceinline__ void sts_bf16_at(u32 addr, float v) {
    unsigned short b; asm("cvt.rn.bf16.f32 %0, %1;" : "=h"(b) : "f"(v));
    asm volatile("st.shared.b16 [%0], %1;" :: "r"(addr), "h"(b));
}
__device__ __forceinline__ u32 pack_bf16x2(float hi, float lo) {
    u32 p; asm("cvt.rn.bf16x2.f32 %0, %1, %2;" : "=r"(p) : "f"(hi), "f"(lo));
    return p;
}
// softplus(100t)/100 = max(t,0) + 0.01*log1p(exp(-|100t|)); correction via LUT
__device__ __forceinline__ float sp_lut(float t, const float2* lut) {
    float s = fminf(fabsf(t) * 3200.0f, 255.9f);   // |100t| * 32
    int i = (int)s;
    float2 e = lut[i];
    return fmaxf(t, 0.f) + 0.01f * (e.x + e.y * (s - (float)i));
}

// ================= pre-pass kernels =================
__global__ void transpose_planes_kernel(const float* __restrict__ planes) {
    int idx = blockIdx.x*blockDim.x + threadIdx.x;
    const int total = 3*GRID_R*GRID_R*NCOMP;
    if (idx >= total) return;
    int c = idx % NCOMP;
    int t = idx / NCOMP;
    int x = t % GRID_R; t /= GRID_R;
    int y = t % GRID_R;
    int p = t / GRID_R;
    g_planesT[idx] = planes[((p*NCOMP + c)*GRID_R + y)*GRID_R + x];
}

__global__ void prep_weights_kernel(const float* __restrict__ lines,
                                    const float* __restrict__ w1,
                                    const float* __restrict__ b1,
                                    const float* __restrict__ w2) {
    int idx = blockIdx.x*blockDim.x + threadIdx.x;
    if (idx < 3*GRID_R*NCOMP) {
        int c = idx % NCOMP;
        int t = idx / NCOMP;
        int z = t % GRID_R;
        int p = t / GRID_R;
        g_linesT[idx] = lines[(p*NCOMP + c)*GRID_R + z];
    }
    if (idx < 256*144) {
        int k = idx % 144, n = idx / 144;
        float v = (k < IN_CH) ? w1[n*IN_CH + k] : ((k == IN_CH) ? b1[n] : 0.f);
        unsigned short b; asm("cvt.rn.bf16.f32 %0, %1;" : "=h"(b) : "f"(v));
        g_w1bf[idx] = b;
    }
    if (idx < 128*256) {
        float v = w2[idx];     // rows 0..127 of [129][256]
        unsigned short b; asm("cvt.rn.bf16.f32 %0, %1;" : "=h"(b) : "f"(v));
        g_w2bf[idx] = b;
    }
}

// ================= main fused kernel =================
__global__ __launch_bounds__(THREADS, 1)
void tensosdf_main(const float* __restrict__ xyz,
                   const float* __restrict__ w2,     // fp32 [129][256] (row 128)
                   const float* __restrict__ b2,
                   float* __restrict__ out)
{
    extern __shared__ __align__(16) char sm[];
    const u32 sa = smem_u32(sm);

    const int tid  = threadIdx.x;
    const int w    = tid >> 5;
    const int lane = tid & 31;
    const int r    = w & 3;       // warp row (32 M-rows)
    const int c    = w >> 2;      // warp col half
    const int g    = lane >> 2;
    const int tg   = lane & 3;

    const u32 sa_xh = sa + XH_OFF;
    const u32 sa_w1 = sa + W1S_OFF;
    const u32 sa_w2 = sa + W2S_OFF;
    float2* lut     = (float2*)(sm + LUT_OFF);
    float*  w2c     = (float*)(sm + W2C_OFF);
    float*  b2s     = (float*)(sm + B2S_OFF);
    float*  c128a   = (float*)(sm + C128A_OFF);
    float*  c128b   = (float*)(sm + C128B_OFF);
    float*  stage   = (float*)(sm + XH_OFF);

    // ---- one-time setup ----
    for (int idx = tid; idx < 4608; idx += THREADS) {       // w1 -> smem, stride 304B
        int n = idx / 18, cc = idx % 18;
        *(uint4*)(sm + W1S_OFF + n*304 + cc*16) = ((const uint4*)g_w1bf)[idx];
    }
    for (int idx = tid; idx < 4096; idx += THREADS) {       // w2 -> smem, stride 528B
        int n = idx >> 5, cc = idx & 31;
        *(uint4*)(sm + W2S_OFF + n*528 + cc*16) = ((const uint4*)g_w2bf)[idx];
    }
    if (tid < 256) {
        float u0 = tid * 0.03125f, u1 = (tid + 1) * 0.03125f;
        float c0v = log1pf(__expf(-u0));
        float c1v = log1pf(__expf(-u1));
        lut[tid] = make_float2(c0v, c1v - c0v);
        w2c[tid] = w2[128*SDF_DIM + tid];
    }
    if (tid < 129) b2s[tid] = b2[tid];
    __syncthreads();

    for (int tile = blockIdx.x; tile < N_TILES; tile += gridDim.x) {
        const int base = tile * TILE_M;

        // ========= gather + embed -> X (bf16 row-major, stride 304B) =========
        {
            const int m0 = w * 16;
            for (int t = 0; t < 16; t++) {
                const int m  = m0 + t;
                const int pt = base + m;
                const u32 xrow = sa_xh + (u32)m * (XSTR*2);
                const float x0 = xyz[pt*3 + 0];
                const float x1 = xyz[pt*3 + 1];
                const float x2 = xyz[pt*3 + 2];

                if (lane < 21) {
                    float v;
                    if (lane < 3) v = (lane == 0) ? x0 : ((lane == 1) ? x1 : x2);
                    else {
                        int tt = lane - 3;
                        int iscos = (tt >= 9);
                        int q = iscos ? tt - 9 : tt;
                        int dim = q / 3, fr = q % 3;
                        float xv = (dim == 0) ? x0 : ((dim == 1) ? x1 : x2);
                        float ang = xv * (float)(1 << fr);
                        v = iscos ? __cosf(ang) : __sinf(ang);
                    }
                    sts_bf16_at(xrow + lane*2, v);
                }
                if (lane < 15)  // k=129 bias channel = 1, k=130..143 = 0
                    sts_bf16_at(xrow + (129 + lane)*2, (lane == 0) ? 1.0f : 0.f);

                #pragma unroll
                for (int p = 0; p < 3; p++) {
                    float px = (p == 2) ? x1 : x0;
                    float py = (p == 0) ? x1 : x2;
                    float pz = (p == 0) ? x2 : ((p == 1) ? x1 : x0);
                    float fx = (px + 1.f) * 0.5f * (GRID_R - 1);
                    float fy = (py + 1.f) * 0.5f * (GRID_R - 1);
                    float fz = (pz + 1.f) * 0.5f * (GRID_R - 1);
                    int ix = min(max((int)floorf(fx), 0), GRID_R - 2);
                    int iy = min(max((int)floorf(fy), 0), GRID_R - 2);
                    int iz = min(max((int)floorf(fz), 0), GRID_R - 2);
                    float tx = fx - (float)ix, ty = fy - (float)iy, tz = fz - (float)iz;
                    const float* pb = g_planesT + ((size_t)(p*GRID_R + iy)*GRID_R + ix)*NCOMP;
                    const float* lb = g_linesT  + (size_t)(p*GRID_R + iz)*NCOMP;
                    float w00 = (1.f - tx) * (1.f - ty);
                    float w01 = tx * (1.f - ty);
                    float w10 = (1.f - tx) * ty;
                    float w11 = tx * ty;
                    #pragma unroll
                    for (int ci = 0; ci < 2; ci++) {
                        int cc = ci*32 + lane;
                        if (cc < NCOMP) {
                            float v00 = pb[cc];
                            float v01 = pb[NCOMP + cc];
                            float v10 = pb[GRID_R*NCOMP + cc];
                            float v11 = pb[GRID_R*NCOMP + NCOMP + cc];
                            float pv = v00*w00 + v01*w01 + v10*w10 + v11*w11;
                            float l0 = lb[cc], l1 = lb[NCOMP + cc];
                            float lv = l0 + tz * (l1 - l0);
                            sts_bf16_at(xrow + (21 + p*36 + cc)*2, pv * lv);
                        }
                    }
                }
            }
        }
        __syncthreads();

        // ========= MMA1: H[128,256] = X[128,144] @ w1^T =========
        float acc[2][16][4];
        #pragma unroll
        for (int mb = 0; mb < 2; mb++)
            #pragma unroll
            for (int nb = 0; nb < 16; nb++)
                #pragma unroll
                for (int k = 0; k < 4; k++) acc[mb][nb][k] = 0.f;

        for (int ks = 0; ks < 9; ks++) {
            u32 a0[4], a1[4];
            const u32 abase = sa_xh + (u32)(32*r + (lane & 15))*304 + ks*32 + (lane >> 4)*16;
            ldsm4(a0, abase);
            ldsm4(a1, abase + 16*304);
            const u32 bk = ks*32 + ((lane >> 3) & 1)*16;
            const u32 bn0 = 128*c + (lane & 7) + ((lane >> 4) & 1)*8;
            #pragma unroll
            for (int q = 0; q < 8; q++) {
                u32 b[4];
                ldsm4(b, sa_w1 + (bn0 + 16*q)*304 + bk);
                mma16816(acc[0][2*q],   a0, b[0], b[1]);
                mma16816(acc[1][2*q],   a1, b[0], b[1]);
                mma16816(acc[0][2*q+1], a0, b[2], b[3]);
                mma16816(acc[1][2*q+1], a1, b[2], b[3]);
            }
        }
        __syncthreads();   // X reads complete; XH becomes H

        // ========= softplus + H store (bf16) + col128 partials =========
        {
            float s128[2][2] = {{0.f,0.f},{0.f,0.f}};   // [mb][row g / g+8]
            #pragma unroll
            for (int mb = 0; mb < 2; mb++) {
                const int R0 = 32*r + 16*mb + g;
                #pragma unroll
                for (int nb = 0; nb < 16; nb++) {
                    const int C = 128*c + 8*nb + 2*tg;
                    float* d = acc[mb][nb];
                    float h0 = sp_lut(d[0], lut);
                    float h1 = sp_lut(d[1], lut);
                    float h2 = sp_lut(d[2], lut);
                    float h3 = sp_lut(d[3], lut);
                    float wc0 = w2c[C], wc1 = w2c[C+1];
                    s128[mb][0] = fmaf(h0, wc0, fmaf(h1, wc1, s128[mb][0]));
                    s128[mb][1] = fmaf(h2, wc0, fmaf(h3, wc1, s128[mb][1]));
                    u32 p0 = pack_bf16x2(h1, h0);
                    u32 p1 = pack_bf16x2(h3, h2);
                    asm volatile("st.shared.b32 [%0], %1;" :: "r"(sa_xh + (u32)R0*528 + C*2), "r"(p0));
                    asm volatile("st.shared.b32 [%0], %1;" :: "r"(sa_xh + (u32)(R0+8)*528 + C*2), "r"(p1));
                }
            }
            // reduce over tg lanes (same g): shfl_xor 1 then 2
            #pragma unroll
            for (int mb = 0; mb < 2; mb++)
                #pragma unroll
                for (int hh = 0; hh < 2; hh++) {
                    float v = s128[mb][hh];
                    v += __shfl_xor_sync(0xffffffffu, v, 1);
                    v += __shfl_xor_sync(0xffffffffu, v, 2);
                    s128[mb][hh] = v;
                }
            if (tg == 0) {
                float* dst = (c == 0) ? c128a : c128b;
                #pragma unroll
                for (int mb = 0; mb < 2; mb++) {
                    dst[32*r + 16*mb + g]     = s128[mb][0];
                    dst[32*r + 16*mb + g + 8] = s128[mb][1];
                }
            }
        }
        __syncthreads();   // H fully written

        // ========= MMA2: O[128,128] = H[128,256] @ w2[0:128]^T =========
        float acc2[2][8][4];
        #pragma unroll
        for (int mb = 0; mb < 2; mb++)
            #pragma unroll
            for (int nb = 0; nb < 8; nb++)
                #pragma unroll
                for (int k = 0; k < 4; k++) acc2[mb][nb][k] = 0.f;

        for (int ks = 0; ks < 16; ks++) {
            u32 a0[4], a1[4];
            const u32 abase = sa_xh + (u32)(32*r + (lane & 15))*528 + ks*32 + (lane >> 4)*16;
            ldsm4(a0, abase);
            ldsm4(a1, abase + 16*528);
            const u32 bk = ks*32 + ((lane >> 3) & 1)*16;
            const u32 bn0 = 64*c + (lane & 7) + ((lane >> 4) & 1)*8;
            #pragma unroll
            for (int q = 0; q < 4; q++) {
                u32 b[4];
                ldsm4(b, sa_w2 + (bn0 + 16*q)*528 + bk);
                mma16816(acc2[0][2*q],   a0, b[0], b[1]);
                mma16816(acc2[1][2*q],   a1, b[0], b[1]);
                mma16816(acc2[0][2*q+1], a0, b[2], b[3]);
                mma16816(acc2[1][2*q+1], a1, b[2], b[3]);
            }
        }
        __syncthreads();   // H reads complete; XH becomes stage

        // ========= stage + coalesced store =========
        #pragma unroll
        for (int mb = 0; mb < 2; mb++) {
            const int R0 = 32*r + 16*mb + g;
            #pragma unroll
            for (int nb = 0; nb < 8; nb++) {
                const int C = 64*c + 8*nb + 2*tg;
                float* d = acc2[mb][nb];
                *(float2*)(stage + R0*130 + C)     = make_float2(d[0] + b2s[C], d[1] + b2s[C+1]);
                *(float2*)(stage + (R0+8)*130 + C) = make_float2(d[2] + b2s[C], d[3] + b2s[C+1]);
            }
        }
        if (tid < 128) stage[tid*130 + 128] = c128a[tid] + c128b[tid] + b2s[128];
        __syncthreads();
        {
            float* op = out + (size_t)base * OUT_CH;
            for (int i = tid; i < 128*OUT_CH; i += THREADS) {
                int rr = i / OUT_CH;
                int cc = i - rr*OUT_CH;
                op[i] = stage[rr*130 + cc];
            }
        }
        __syncthreads();   // stage reads done before next gather overwrites XH
    }
}

// ================= launch =================
extern "C" void kernel_launch(void* const* d_in, const int* in_sizes, int n_in,
                              void* d_out, int out_size) {
    const float* xyz    = (const float*)d_in[0];
    const float* planes = (const float*)d_in[1];
    const float* lines  = (const float*)d_in[2];
    const float* w1     = (const float*)d_in[3];
    const float* b1     = (const float*)d_in[4];
    const float* w2     = (const float*)d_in[5];
    const float* b2     = (const float*)d_in[6];
    float* out = (float*)d_out;

    int sms = 148;
    cudaDeviceGetAttribute(&sms, cudaDevAttrMultiProcessorCount, 0);

    const int ptot = 3*GRID_R*GRID_R*NCOMP;
    transpose_planes_kernel<<<(ptot + 255)/256, 256>>>(planes);
    prep_weights_kernel<<<(256*144 + 255)/256, 256>>>(lines, w1, b1, w2);

    cudaFuncSetAttribute(tensosdf_main, cudaFuncAttributeMaxDynamicSharedMemorySize, SMEM_TOTAL);
    tensosdf_main<<<sms, THREADS, SMEM_TOTAL>>>(xyz, w2, b2, out);
}

// round 5
// speedup vs baseline: 13.6743x; 1.3659x over previous
#include <cuda_runtime.h>
#include <cuda_bf16.h>
#include <math.h>
#include <cstdint>

#define N_PTS   524288
#define GRID_R  300
#define NCOMP   36
#define SDF_DIM 256
#define IN_CH   129
#define OUT_CH  129
#define TILE_M  128
#define N_TILES (N_PTS / TILE_M)      // 4096
#define THREADS 256                   // 8 warps

// ---- kernel B smem map (bytes) ----
#define W1S_OFF  0                    // 256 x 304B = 77824
#define W2S_OFF  77824                // 128 x 528B = 67584
#define HS_OFF   145408               // H 128 x 528B = 67584 (stage overlays)
#define LUT_OFF  212992               // 256 * 8
#define W2C_OFF  215040               // 256 * 4
#define B2S_OFF  216064               // 132 * 4
#define C128A_OFF 216592              // 128 * 4
#define C128B_OFF 217104              // 128 * 4
#define SMEM_B   217616

typedef unsigned int u32;

__device__ float g_planesT[3*GRID_R*GRID_R*NCOMP];
__device__ float g_linesT [3*GRID_R*NCOMP];
__device__ __align__(16) unsigned short g_w1bf[256*144];   // [n][k], k129=b1, 130..143=0
__device__ __align__(16) unsigned short g_w2bf[128*256];   // [n][k]
__device__ uint4 g_X[N_TILES*8*9*32];                      // A-fragments, 151MB

__device__ __forceinline__ u32 smem_u32(const void* p) {
    u32 a; asm("{ .reg .u64 t; cvta.to.shared.u64 t, %1; cvt.u32.u64 %0, t; }" : "=r"(a) : "l"(p));
    return a;
}
__device__ __forceinline__ void ldsm4(u32* r, u32 addr) {
    asm volatile("ldmatrix.sync.aligned.m8n8.x4.shared.b16 {%0,%1,%2,%3}, [%4];"
        : "=r"(r[0]), "=r"(r[1]), "=r"(r[2]), "=r"(r[3]) : "r"(addr));
}
__device__ __forceinline__ void mma16816(float* c, const u32* a, u32 b0, u32 b1) {
    asm volatile("mma.sync.aligned.m16n8k16.row.col.f32.bf16.bf16.f32 "
        "{%0,%1,%2,%3}, {%4,%5,%6,%7}, {%8,%9}, {%0,%1,%2,%3};"
        : "+f"(c[0]), "+f"(c[1]), "+f"(c[2]), "+f"(c[3])
        : "r"(a[0]), "r"(a[1]), "r"(a[2]), "r"(a[3]), "r"(b0), "r"(b1));
}
__device__ __forceinline__ void sts_bf16_at(u32 addr, float v) {
    unsigned short b; asm("cvt.rn.bf16.f32 %0, %1;" : "=h"(b) : "f"(v));
    asm volatile("st.shared.b16 [%0], %1;" :: "r"(addr), "h"(b));
}
__device__ __forceinline__ u32 lds_u32(u32 addr) {
    u32 v; asm volatile("ld.shared.b32 %0, [%1];" : "=r"(v) : "r"(addr));
    return v;
}
__device__ __forceinline__ u32 pack_bf16x2(float hi, float lo) {
    u32 p; asm("cvt.rn.bf16x2.f32 %0, %1, %2;" : "=r"(p) : "f"(hi), "f"(lo));
    return p;
}
__device__ __forceinline__ float sp_lut(float t, const float2* lut) {
    float s = fminf(fabsf(t) * 3200.0f, 255.9f);
    int i = (int)s;
    float2 e = lut[i];
    return fmaxf(t, 0.f) + 0.01f * (e.x + e.y * (s - (float)i));
}

// ================= pre-pass: tiled transpose =================
__global__ void transpose_planes_kernel(const float* __restrict__ planes) {
    __shared__ float t[36*301];
    const int b = blockIdx.x;            // p*300 + y
    const int p = b / GRID_R;
    const int y = b % GRID_R;
    const int tid = threadIdx.x;
    for (int idx = tid; idx < 36*GRID_R; idx += blockDim.x) {
        int c = idx / GRID_R, x = idx % GRID_R;
        t[c*301 + x] = planes[((size_t)(p*NCOMP + c)*GRID_R + y)*GRID_R + x];
    }
    __syncthreads();
    float* dst = g_planesT + (size_t)(p*GRID_R + y)*GRID_R*NCOMP;
    for (int idx = tid; idx < GRID_R*36; idx += blockDim.x) {
        int x = idx / 36, c = idx % 36;
        dst[idx] = t[c*301 + x];
    }
}

__global__ void prep_weights_kernel(const float* __restrict__ lines,
                                    const float* __restrict__ w1,
                                    const float* __restrict__ b1,
                                    const float* __restrict__ w2) {
    int idx = blockIdx.x*blockDim.x + threadIdx.x;
    if (idx < 3*GRID_R*NCOMP) {
        int c = idx % NCOMP;
        int t = idx / NCOMP;
        int z = t % GRID_R;
        int p = t / GRID_R;
        g_linesT[idx] = lines[(p*NCOMP + c)*GRID_R + z];
    }
    if (idx < 256*144) {
        int k = idx % 144, n = idx / 144;
        float v = (k < IN_CH) ? w1[n*IN_CH + k] : ((k == IN_CH) ? b1[n] : 0.f);
        unsigned short b; asm("cvt.rn.bf16.f32 %0, %1;" : "=h"(b) : "f"(v));
        g_w1bf[idx] = b;
    }
    if (idx < 128*256) {
        float v = w2[idx];
        unsigned short b; asm("cvt.rn.bf16.f32 %0, %1;" : "=h"(b) : "f"(v));
        g_w2bf[idx] = b;
    }
}

// ================= kernel A: gather + embed -> fragment-packed X =================
__global__ __launch_bounds__(THREADS)
void gather_kernel(const float* __restrict__ xyz) {
    extern __shared__ __align__(16) char sg[];
    const u32 sa = smem_u32(sg);

    const int tid  = threadIdx.x;
    const int w    = tid >> 5;
    const int lane = tid & 31;
    const int blk  = blockIdx.x;           // tile index
    const int base = blk * TILE_M;
    const u32 rb   = sa + (u32)w * (16*304);   // this warp's 16-row buffer

    // gather 16 points into row buffer (bf16, stride 304B)
    for (int t = 0; t < 16; t++) {
        const int pt = base + w*16 + t;
        const u32 xrow = rb + (u32)t * 304;
        const float x0 = xyz[pt*3 + 0];
        const float x1 = xyz[pt*3 + 1];
        const float x2 = xyz[pt*3 + 2];

        if (lane < 21) {
            float v;
            if (lane < 3) v = (lane == 0) ? x0 : ((lane == 1) ? x1 : x2);
            else {
                int tt = lane - 3;
                int iscos = (tt >= 9);
                int q = iscos ? tt - 9 : tt;
                int dim = q / 3, fr = q % 3;
                float xv = (dim == 0) ? x0 : ((dim == 1) ? x1 : x2);
                float ang = xv * (float)(1 << fr);
                v = iscos ? __cosf(ang) : __sinf(ang);
            }
            sts_bf16_at(xrow + lane*2, v);
        }
        if (lane < 15)  // k=129 bias channel = 1, 130..143 = 0
            sts_bf16_at(xrow + (129 + lane)*2, (lane == 0) ? 1.0f : 0.f);

        #pragma unroll
        for (int p = 0; p < 3; p++) {
            float px = (p == 2) ? x1 : x0;
            float py = (p == 0) ? x1 : x2;
            float pz = (p == 0) ? x2 : ((p == 1) ? x1 : x0);
            float fx = (px + 1.f) * 0.5f * (GRID_R - 1);
            float fy = (py + 1.f) * 0.5f * (GRID_R - 1);
            float fz = (pz + 1.f) * 0.5f * (GRID_R - 1);
            int ix = min(max((int)floorf(fx), 0), GRID_R - 2);
            int iy = min(max((int)floorf(fy), 0), GRID_R - 2);
            int iz = min(max((int)floorf(fz), 0), GRID_R - 2);
            float tx = fx - (float)ix, ty = fy - (float)iy, tz = fz - (float)iz;
            const float* pb = g_planesT + ((size_t)(p*GRID_R + iy)*GRID_R + ix)*NCOMP;
            const float* lb = g_linesT  + (size_t)(p*GRID_R + iz)*NCOMP;
            float w00 = (1.f - tx) * (1.f - ty);
            float w01 = tx * (1.f - ty);
            float w10 = (1.f - tx) * ty;
            float w11 = tx * ty;
            #pragma unroll
            for (int ci = 0; ci < 2; ci++) {
                int cc = ci*32 + lane;
                if (cc < NCOMP) {
                    float v00 = pb[cc];
                    float v01 = pb[NCOMP + cc];
                    float v10 = pb[GRID_R*NCOMP + cc];
                    float v11 = pb[GRID_R*NCOMP + NCOMP + cc];
                    float pv = v00*w00 + v01*w01 + v10*w10 + v11*w11;
                    float l0 = lb[cc], l1 = lb[NCOMP + cc];
                    float lv = l0 + tz * (l1 - l0);
                    sts_bf16_at(xrow + (21 + p*36 + cc)*2, pv * lv);
                }
            }
        }
    }
    __syncwarp();

    // repack into A-fragment order: frag (strip = blk*8+w, ks); lane holds a0..a3
    const int g  = lane >> 2;
    const int tg = lane & 3;
    uint4* dst = g_X + ((size_t)(blk*8 + w)*9)*32 + lane;
    #pragma unroll
    for (int ks = 0; ks < 9; ks++) {
        u32 a0 = lds_u32(rb + (u32)g*304     + ks*32 + tg*4);
        u32 a1 = lds_u32(rb + (u32)(g+8)*304 + ks*32 + tg*4);
        u32 a2 = lds_u32(rb + (u32)g*304     + ks*32 + tg*4 + 16);
        u32 a3 = lds_u32(rb + (u32)(g+8)*304 + ks*32 + tg*4 + 16);
        dst[ks*32] = make_uint4(a0, a1, a2, a3);
    }
}

// ================= kernel B: MLP (tensor cores) =================
__global__ __launch_bounds__(THREADS, 1)
void mlp_kernel(const float* __restrict__ w2,
                const float* __restrict__ b2,
                float* __restrict__ out)
{
    extern __shared__ __align__(16) char sm[];
    const u32 sa = smem_u32(sm);

    const int tid  = threadIdx.x;
    const int w    = tid >> 5;
    const int lane = tid & 31;
    const int r    = w & 3;
    const int c    = w >> 2;
    const int g    = lane >> 2;
    const int tg   = lane & 3;

    const u32 sa_w1 = sa + W1S_OFF;
    const u32 sa_w2 = sa + W2S_OFF;
    const u32 sa_h  = sa + HS_OFF;
    float2* lut   = (float2*)(sm + LUT_OFF);
    float*  w2c   = (float*)(sm + W2C_OFF);
    float*  b2s   = (float*)(sm + B2S_OFF);
    float*  c128a = (float*)(sm + C128A_OFF);
    float*  c128b = (float*)(sm + C128B_OFF);
    float*  stage = (float*)(sm + HS_OFF);

    for (int idx = tid; idx < 4608; idx += THREADS) {        // w1 -> smem, stride 304B
        int n = idx / 18, cc = idx % 18;
        *(uint4*)(sm + W1S_OFF + n*304 + cc*16) = ((const uint4*)g_w1bf)[idx];
    }
    for (int idx = tid; idx < 4096; idx += THREADS) {        // w2 -> smem, stride 528B
        int n = idx >> 5, cc = idx & 31;
        *(uint4*)(sm + W2S_OFF + n*528 + cc*16) = ((const uint4*)g_w2bf)[idx];
    }
    if (tid < 256) {
        float u0 = tid * 0.03125f, u1 = (tid + 1) * 0.03125f;
        float c0v = log1pf(__expf(-u0));
        float c1v = log1pf(__expf(-u1));
        lut[tid] = make_float2(c0v, c1v - c0v);
        w2c[tid] = w2[128*SDF_DIM + tid];
    }
    if (tid < 129) b2s[tid] = b2[tid];
    __syncthreads();

    for (int tile = blockIdx.x; tile < N_TILES; tile += gridDim.x) {
        const int base = tile * TILE_M;

        // ---- A-fragments direct from global (coalesced LDG.128) ----
        uint4 af[2][9];
        #pragma unroll
        for (int mb = 0; mb < 2; mb++) {
            const uint4* src = g_X + ((size_t)(tile*8 + 2*r + mb)*9)*32 + lane;
            #pragma unroll
            for (int ks = 0; ks < 9; ks++) af[mb][ks] = src[ks*32];
        }

        // ---- MMA1: H[128,256] = X @ w1^T ----
        float acc[2][16][4];
        #pragma unroll
        for (int mb = 0; mb < 2; mb++)
            #pragma unroll
            for (int nb = 0; nb < 16; nb++)
                #pragma unroll
                for (int k = 0; k < 4; k++) acc[mb][nb][k] = 0.f;

        const u32 bn0 = 128*c + (lane & 7) + ((lane >> 4) & 1)*8;
        #pragma unroll
        for (int ks = 0; ks < 9; ks++) {
            const u32 bk = ks*32 + ((lane >> 3) & 1)*16;
            #pragma unroll
            for (int q = 0; q < 8; q++) {
                u32 b[4];
                ldsm4(b, sa_w1 + (bn0 + 16*q)*304 + bk);
                mma16816(acc[0][2*q],   (const u32*)&af[0][ks], b[0], b[1]);
                mma16816(acc[1][2*q],   (const u32*)&af[1][ks], b[0], b[1]);
                mma16816(acc[0][2*q+1], (const u32*)&af[0][ks], b[2], b[3]);
                mma16816(acc[1][2*q+1], (const u32*)&af[1][ks], b[2], b[3]);
            }
        }

        // ---- softplus + H store (bf16) + col128 partials ----
        {
            float s128[2][2] = {{0.f,0.f},{0.f,0.f}};
            #pragma unroll
            for (int mb = 0; mb < 2; mb++) {
                const int R0 = 32*r + 16*mb + g;
                #pragma unroll
                for (int nb = 0; nb < 16; nb++) {
                    const int C = 128*c + 8*nb + 2*tg;
                    float* d = acc[mb][nb];
                    float h0 = sp_lut(d[0], lut);
                    float h1 = sp_lut(d[1], lut);
                    float h2 = sp_lut(d[2], lut);
                    float h3 = sp_lut(d[3], lut);
                    float wc0 = w2c[C], wc1 = w2c[C+1];
                    s128[mb][0] = fmaf(h0, wc0, fmaf(h1, wc1, s128[mb][0]));
                    s128[mb][1] = fmaf(h2, wc0, fmaf(h3, wc1, s128[mb][1]));
                    u32 p0 = pack_bf16x2(h1, h0);
                    u32 p1 = pack_bf16x2(h3, h2);
                    asm volatile("st.shared.b32 [%0], %1;" :: "r"(sa_h + (u32)R0*528 + C*2), "r"(p0));
                    asm volatile("st.shared.b32 [%0], %1;" :: "r"(sa_h + (u32)(R0+8)*528 + C*2), "r"(p1));
                }
            }
            #pragma unroll
            for (int mb = 0; mb < 2; mb++)
                #pragma unroll
                for (int hh = 0; hh < 2; hh++) {
                    float v = s128[mb][hh];
                    v += __shfl_xor_sync(0xffffffffu, v, 1);
                    v += __shfl_xor_sync(0xffffffffu, v, 2);
                    s128[mb][hh] = v;
                }
            if (tg == 0) {
                float* dst = (c == 0) ? c128a : c128b;
                #pragma unroll
                for (int mb = 0; mb < 2; mb++) {
                    dst[32*r + 16*mb + g]     = s128[mb][0];
                    dst[32*r + 16*mb + g + 8] = s128[mb][1];
                }
            }
        }
        __syncthreads();   // H + c128 written

        // ---- MMA2: O[128,128] = H @ w2[0:128]^T ----
        float acc2[2][8][4];
        #pragma unroll
        for (int mb = 0; mb < 2; mb++)
            #pragma unroll
            for (int nb = 0; nb < 8; nb++)
                #pragma unroll
                for (int k = 0; k < 4; k++) acc2[mb][nb][k] = 0.f;

        const u32 bn0b = 64*c + (lane & 7) + ((lane >> 4) & 1)*8;
        for (int ks = 0; ks < 16; ks++) {
            u32 a0[4], a1[4];
            const u32 abase = sa_h + (u32)(32*r + (lane & 15))*528 + ks*32 + (lane >> 4)*16;
            ldsm4(a0, abase);
            ldsm4(a1, abase + 16*528);
            const u32 bk = ks*32 + ((lane >> 3) & 1)*16;
            #pragma unroll
            for (int q = 0; q < 4; q++) {
                u32 b[4];
                ldsm4(b, sa_w2 + (bn0b + 16*q)*528 + bk);
                mma16816(acc2[0][2*q],   a0, b[0], b[1]);
                mma16816(acc2[1][2*q],   a1, b[0], b[1]);
                mma16816(acc2[0][2*q+1], a0, b[2], b[3]);
                mma16816(acc2[1][2*q+1], a1, b[2], b[3]);
            }
        }
        __syncthreads();   // H reads done; region becomes stage

        // ---- stage + coalesced store ----
        #pragma unroll
        for (int mb = 0; mb < 2; mb++) {
            const int R0 = 32*r + 16*mb + g;
            #pragma unroll
            for (int nb = 0; nb < 8; nb++) {
                const int C = 64*c + 8*nb + 2*tg;
                float* d = acc2[mb][nb];
                *(float2*)(stage + R0*130 + C)     = make_float2(d[0] + b2s[C], d[1] + b2s[C+1]);
                *(float2*)(stage + (R0+8)*130 + C) = make_float2(d[2] + b2s[C], d[3] + b2s[C+1]);
            }
        }
        if (tid < 128) stage[tid*130 + 128] = c128a[tid] + c128b[tid] + b2s[128];
        __syncthreads();
        {
            float* op = out + (size_t)base * OUT_CH;
            for (int i = tid; i < 128*OUT_CH; i += THREADS) {
                int rr = i / OUT_CH;
                int cc = i - rr*OUT_CH;
                op[i] = stage[rr*130 + cc];
            }
        }
        __syncthreads();
    }
}

// ================= launch =================
extern "C" void kernel_launch(void* const* d_in, const int* in_sizes, int n_in,
                              void* d_out, int out_size) {
    const float* xyz    = (const float*)d_in[0];
    const float* planes = (const float*)d_in[1];
    const float* lines  = (const float*)d_in[2];
    const float* w1     = (const float*)d_in[3];
    const float* b1     = (const float*)d_in[4];
    const float* w2     = (const float*)d_in[5];
    const float* b2     = (const float*)d_in[6];
    float* out = (float*)d_out;

    int sms = 148;
    cudaDeviceGetAttribute(&sms, cudaDevAttrMultiProcessorCount, 0);

    transpose_planes_kernel<<<3*GRID_R, 256>>>(planes);
    prep_weights_kernel<<<(256*144 + 255)/256, 256>>>(lines, w1, b1, w2);
    gather_kernel<<<N_TILES, THREADS, 8*16*304>>>(xyz);

    cudaFuncSetAttribute(mlp_kernel, cudaFuncAttributeMaxDynamicSharedMemorySize, SMEM_B);
    mlp_kernel<<<sms, THREADS, SMEM_B>>>(w2, b2, out);
}

// round 6
// speedup vs baseline: 14.1645x; 1.0358x over previous
#include <cuda_runtime.h>
#include <cuda_bf16.h>
#include <math.h>
#include <cstdint>

#define N_PTS   524288
#define GRID_R  300
#define NCOMP   36
#define SDF_DIM 256
#define IN_CH   129
#define OUT_CH  129
#define TILE_M  128
#define N_TILES (N_PTS / TILE_M)      // 4096

#define GTHREADS 256                  // gather kernel
#define MTHREADS 512                  // mlp kernel: 16 warps

// ---- mlp kernel smem map (bytes) ----
#define W1S_OFF  0                    // 256 x 304B = 77824
#define W2S_OFF  77824                // 128 x 528B = 67584
#define HS_OFF   145408               // H 128 x 528B = 67584 (stage overlays)
#define LUT_OFF  212992               // 256 * 8
#define W2C_OFF  215040               // 256 * 4
#define B2S_OFF  216064               // 132 * 4
#define C128_OFF 216592               // 4 * 128 * 4 = 2048
#define SMEM_B   218640

typedef unsigned int u32;

__device__ float g_planesT[3*GRID_R*GRID_R*NCOMP];
__device__ float g_linesT [3*GRID_R*NCOMP];
__device__ __align__(16) unsigned short g_w1bf[256*144];   // [n][k], k129=b1, 130..143=0
__device__ __align__(16) unsigned short g_w2bf[128*256];   // [n][k]
__device__ uint4 g_X[N_TILES*8*9*32];                      // A-fragments, 151MB

__device__ __forceinline__ u32 smem_u32(const void* p) {
    u32 a; asm("{ .reg .u64 t; cvta.to.shared.u64 t, %1; cvt.u32.u64 %0, t; }" : "=r"(a) : "l"(p));
    return a;
}
__device__ __forceinline__ void ldsm4(u32* r, u32 addr) {
    asm volatile("ldmatrix.sync.aligned.m8n8.x4.shared.b16 {%0,%1,%2,%3}, [%4];"
        : "=r"(r[0]), "=r"(r[1]), "=r"(r[2]), "=r"(r[3]) : "r"(addr));
}
__device__ __forceinline__ void mma16816(float* c, const u32* a, u32 b0, u32 b1) {
    asm volatile("mma.sync.aligned.m16n8k16.row.col.f32.bf16.bf16.f32 "
        "{%0,%1,%2,%3}, {%4,%5,%6,%7}, {%8,%9}, {%0,%1,%2,%3};"
        : "+f"(c[0]), "+f"(c[1]), "+f"(c[2]), "+f"(c[3])
        : "r"(a[0]), "r"(a[1]), "r"(a[2]), "r"(a[3]), "r"(b0), "r"(b1));
}
__device__ __forceinline__ void sts_bf16_at(u32 addr, float v) {
    unsigned short b; asm("cvt.rn.bf16.f32 %0, %1;" : "=h"(b) : "f"(v));
    asm volatile("st.shared.b16 [%0], %1;" :: "r"(addr), "h"(b));
}
__device__ __forceinline__ u32 lds_u32(u32 addr) {
    u32 v; asm volatile("ld.shared.b32 %0, [%1];" : "=r"(v) : "r"(addr));
    return v;
}
__device__ __forceinline__ u32 pack_bf16x2(float hi, float lo) {
    u32 p; asm("cvt.rn.bf16x2.f32 %0, %1, %2;" : "=r"(p) : "f"(hi), "f"(lo));
    return p;
}
__device__ __forceinline__ float sp_lut(float t, const float2* lut) {
    float s = fminf(fabsf(t) * 3200.0f, 255.9f);
    int i = (int)s;
    float2 e = lut[i];
    return fmaxf(t, 0.f) + 0.01f * (e.x + e.y * (s - (float)i));
}

// ================= pre-pass: tiled transpose =================
__global__ void transpose_planes_kernel(const float* __restrict__ planes) {
    __shared__ float t[36*301];
    const int b = blockIdx.x;            // p*300 + y
    const int p = b / GRID_R;
    const int y = b % GRID_R;
    const int tid = threadIdx.x;
    for (int idx = tid; idx < 36*GRID_R; idx += blockDim.x) {
        int c = idx / GRID_R, x = idx % GRID_R;
        t[c*301 + x] = planes[((size_t)(p*NCOMP + c)*GRID_R + y)*GRID_R + x];
    }
    __syncthreads();
    float* dst = g_planesT + (size_t)(p*GRID_R + y)*GRID_R*NCOMP;
    for (int idx = tid; idx < GRID_R*36; idx += blockDim.x) {
        int x = idx / 36, c = idx % 36;
        dst[idx] = t[c*301 + x];
    }
}

__global__ void prep_weights_kernel(const float* __restrict__ lines,
                                    const float* __restrict__ w1,
                                    const float* __restrict__ b1,
                                    const float* __restrict__ w2) {
    int idx = blockIdx.x*blockDim.x + threadIdx.x;
    if (idx < 3*GRID_R*NCOMP) {
        int c = idx % NCOMP;
        int t = idx / NCOMP;
        int z = t % GRID_R;
        int p = t / GRID_R;
        g_linesT[idx] = lines[(p*NCOMP + c)*GRID_R + z];
    }
    if (idx < 256*144) {
        int k = idx % 144, n = idx / 144;
        float v = (k < IN_CH) ? w1[n*IN_CH + k] : ((k == IN_CH) ? b1[n] : 0.f);
        unsigned short b; asm("cvt.rn.bf16.f32 %0, %1;" : "=h"(b) : "f"(v));
        g_w1bf[idx] = b;
    }
    if (idx < 128*256) {
        float v = w2[idx];
        unsigned short b; asm("cvt.rn.bf16.f32 %0, %1;" : "=h"(b) : "f"(v));
        g_w2bf[idx] = b;
    }
}

// ================= kernel A: gather + embed -> fragment-packed X =================
__global__ __launch_bounds__(GTHREADS)
void gather_kernel(const float* __restrict__ xyz) {
    extern __shared__ __align__(16) char sg[];
    const u32 sa = smem_u32(sg);

    const int tid  = threadIdx.x;
    const int w    = tid >> 5;
    const int lane = tid & 31;
    const int blk  = blockIdx.x;
    const int base = blk * TILE_M;
    const u32 rb   = sa + (u32)w * (16*304);

    for (int t = 0; t < 16; t++) {
        const int pt = base + w*16 + t;
        const u32 xrow = rb + (u32)t * 304;
        const float x0 = xyz[pt*3 + 0];
        const float x1 = xyz[pt*3 + 1];
        const float x2 = xyz[pt*3 + 2];

        if (lane < 21) {
            float v;
            if (lane < 3) v = (lane == 0) ? x0 : ((lane == 1) ? x1 : x2);
            else {
                int tt = lane - 3;
                int iscos = (tt >= 9);
                int q = iscos ? tt - 9 : tt;
                int dim = q / 3, fr = q % 3;
                float xv = (dim == 0) ? x0 : ((dim == 1) ? x1 : x2);
                float ang = xv * (float)(1 << fr);
                v = iscos ? __cosf(ang) : __sinf(ang);
            }
            sts_bf16_at(xrow + lane*2, v);
        }
        if (lane < 15)
            sts_bf16_at(xrow + (129 + lane)*2, (lane == 0) ? 1.0f : 0.f);

        #pragma unroll
        for (int p = 0; p < 3; p++) {
            float px = (p == 2) ? x1 : x0;
            float py = (p == 0) ? x1 : x2;
            float pz = (p == 0) ? x2 : ((p == 1) ? x1 : x0);
            float fx = (px + 1.f) * 0.5f * (GRID_R - 1);
            float fy = (py + 1.f) * 0.5f * (GRID_R - 1);
            float fz = (pz + 1.f) * 0.5f * (GRID_R - 1);
            int ix = min(max((int)floorf(fx), 0), GRID_R - 2);
            int iy = min(max((int)floorf(fy), 0), GRID_R - 2);
            int iz = min(max((int)floorf(fz), 0), GRID_R - 2);
            float tx = fx - (float)ix, ty = fy - (float)iy, tz = fz - (float)iz;
            const float* pb = g_planesT + ((size_t)(p*GRID_R + iy)*GRID_R + ix)*NCOMP;
            const float* lb = g_linesT  + (size_t)(p*GRID_R + iz)*NCOMP;
            float w00 = (1.f - tx) * (1.f - ty);
            float w01 = tx * (1.f - ty);
            float w10 = (1.f - tx) * ty;
            float w11 = tx * ty;
            #pragma unroll
            for (int ci = 0; ci < 2; ci++) {
                int cc = ci*32 + lane;
                if (cc < NCOMP) {
                    float v00 = pb[cc];
                    float v01 = pb[NCOMP + cc];
                    float v10 = pb[GRID_R*NCOMP + cc];
                    float v11 = pb[GRID_R*NCOMP + NCOMP + cc];
                    float pv = v00*w00 + v01*w01 + v10*w10 + v11*w11;
                    float l0 = lb[cc], l1 = lb[NCOMP + cc];
                    float lv = l0 + tz * (l1 - l0);
                    sts_bf16_at(xrow + (21 + p*36 + cc)*2, pv * lv);
                }
            }
        }
    }
    __syncwarp();

    const int g  = lane >> 2;
    const int tg = lane & 3;
    uint4* dst = g_X + ((size_t)(blk*8 + w)*9)*32 + lane;
    #pragma unroll
    for (int ks = 0; ks < 9; ks++) {
        u32 a0 = lds_u32(rb + (u32)g*304     + ks*32 + tg*4);
        u32 a1 = lds_u32(rb + (u32)(g+8)*304 + ks*32 + tg*4);
        u32 a2 = lds_u32(rb + (u32)g*304     + ks*32 + tg*4 + 16);
        u32 a3 = lds_u32(rb + (u32)(g+8)*304 + ks*32 + tg*4 + 16);
        dst[ks*32] = make_uint4(a0, a1, a2, a3);
    }
}

// ================= kernel B: MLP, 16 warps =================
__global__ __launch_bounds__(MTHREADS, 1)
void mlp_kernel(const float* __restrict__ w2,
                const float* __restrict__ b2,
                float* __restrict__ out)
{
    extern __shared__ __align__(16) char sm[];
    const u32 sa = smem_u32(sm);

    const int tid  = threadIdx.x;
    const int w    = tid >> 5;
    const int lane = tid & 31;
    const int r    = w & 3;        // row group: rows 32r..32r+31
    const int c    = w >> 2;       // col group 0..3
    const int g    = lane >> 2;
    const int tg   = lane & 3;

    const u32 sa_w1 = sa + W1S_OFF;
    const u32 sa_w2 = sa + W2S_OFF;
    const u32 sa_h  = sa + HS_OFF;
    float2* lut   = (float2*)(sm + LUT_OFF);
    float*  w2c   = (float*)(sm + W2C_OFF);
    float*  b2s   = (float*)(sm + B2S_OFF);
    float*  c128  = (float*)(sm + C128_OFF);   // [4][128]
    float*  stage = (float*)(sm + HS_OFF);

    for (int idx = tid; idx < 4608; idx += MTHREADS) {
        int n = idx / 18, cc = idx % 18;
        *(uint4*)(sm + W1S_OFF + n*304 + cc*16) = ((const uint4*)g_w1bf)[idx];
    }
    for (int idx = tid; idx < 4096; idx += MTHREADS) {
        int n = idx >> 5, cc = idx & 31;
        *(uint4*)(sm + W2S_OFF + n*528 + cc*16) = ((const uint4*)g_w2bf)[idx];
    }
    if (tid < 256) {
        float u0 = tid * 0.03125f, u1 = (tid + 1) * 0.03125f;
        float c0v = log1pf(__expf(-u0));
        float c1v = log1pf(__expf(-u1));
        lut[tid] = make_float2(c0v, c1v - c0v);
        w2c[tid] = w2[128*SDF_DIM + tid];
    }
    if (tid < 129) b2s[tid] = b2[tid];
    __syncthreads();

    for (int tile = blockIdx.x; tile < N_TILES; tile += gridDim.x) {
        const int base = tile * TILE_M;

        // ---- MMA1: rows 32r..+31, cols 64c..+63 ----
        float acc[2][8][4];
        #pragma unroll
        for (int mb = 0; mb < 2; mb++)
            #pragma unroll
            for (int nb = 0; nb < 8; nb++)
                #pragma unroll
                for (int k = 0; k < 4; k++) acc[mb][nb][k] = 0.f;

        const uint4* asrc0 = g_X + ((size_t)(tile*8 + 2*r    )*9)*32 + lane;
        const uint4* asrc1 = g_X + ((size_t)(tile*8 + 2*r + 1)*9)*32 + lane;
        const u32 bn0 = 64*c + (lane & 7) + ((lane >> 4) & 1)*8;

        uint4 af0 = asrc0[0];
        uint4 af1 = asrc1[0];
        #pragma unroll
        for (int ks = 0; ks < 9; ks++) {
            uint4 nf0, nf1;
            if (ks < 8) { nf0 = asrc0[(ks+1)*32]; nf1 = asrc1[(ks+1)*32]; }
            const u32 bk = ks*32 + ((lane >> 3) & 1)*16;
            #pragma unroll
            for (int q = 0; q < 4; q++) {
                u32 b[4];
                ldsm4(b, sa_w1 + (bn0 + 16*q)*304 + bk);
                mma16816(acc[0][2*q],   (const u32*)&af0, b[0], b[1]);
                mma16816(acc[1][2*q],   (const u32*)&af1, b[0], b[1]);
                mma16816(acc[0][2*q+1], (const u32*)&af0, b[2], b[3]);
                mma16816(acc[1][2*q+1], (const u32*)&af1, b[2], b[3]);
            }
            af0 = nf0; af1 = nf1;
        }

        // ---- softplus + H store (bf16) + col128 partials ----
        {
            float s128[2][2] = {{0.f,0.f},{0.f,0.f}};
            #pragma unroll
            for (int mb = 0; mb < 2; mb++) {
                const int R0 = 32*r + 16*mb + g;
                #pragma unroll
                for (int nb = 0; nb < 8; nb++) {
                    const int C = 64*c + 8*nb + 2*tg;
                    float* d = acc[mb][nb];
                    float h0 = sp_lut(d[0], lut);
                    float h1 = sp_lut(d[1], lut);
                    float h2 = sp_lut(d[2], lut);
                    float h3 = sp_lut(d[3], lut);
                    float wc0 = w2c[C], wc1 = w2c[C+1];
                    s128[mb][0] = fmaf(h0, wc0, fmaf(h1, wc1, s128[mb][0]));
                    s128[mb][1] = fmaf(h2, wc0, fmaf(h3, wc1, s128[mb][1]));
                    u32 p0 = pack_bf16x2(h1, h0);
                    u32 p1 = pack_bf16x2(h3, h2);
                    asm volatile("st.shared.b32 [%0], %1;" :: "r"(sa_h + (u32)R0*528 + C*2), "r"(p0));
                    asm volatile("st.shared.b32 [%0], %1;" :: "r"(sa_h + (u32)(R0+8)*528 + C*2), "r"(p1));
                }
            }
            #pragma unroll
            for (int mb = 0; mb < 2; mb++)
                #pragma unroll
                for (int hh = 0; hh < 2; hh++) {
                    float v = s128[mb][hh];
                    v += __shfl_xor_sync(0xffffffffu, v, 1);
                    v += __shfl_xor_sync(0xffffffffu, v, 2);
                    s128[mb][hh] = v;
                }
            if (tg == 0) {
                float* dst = c128 + c*128;
                #pragma unroll
                for (int mb = 0; mb < 2; mb++) {
                    dst[32*r + 16*mb + g]     = s128[mb][0];
                    dst[32*r + 16*mb + g + 8] = s128[mb][1];
                }
            }
        }
        __syncthreads();   // H + c128 written

        // ---- MMA2: rows 32r..+31, cols 32c..+31 ----
        float acc2[2][4][4];
        #pragma unroll
        for (int mb = 0; mb < 2; mb++)
            #pragma unroll
            for (int nb = 0; nb < 4; nb++)
                #pragma unroll
                for (int k = 0; k < 4; k++) acc2[mb][nb][k] = 0.f;

        const u32 bn0b = 32*c + (lane & 7) + ((lane >> 4) & 1)*8;
        #pragma unroll 4
        for (int ks = 0; ks < 16; ks++) {
            u32 a0[4], a1[4];
            const u32 abase = sa_h + (u32)(32*r + (lane & 15))*528 + ks*32 + (lane >> 4)*16;
            ldsm4(a0, abase);
            ldsm4(a1, abase + 16*528);
            const u32 bk = ks*32 + ((lane >> 3) & 1)*16;
            #pragma unroll
            for (int q = 0; q < 2; q++) {
                u32 b[4];
                ldsm4(b, sa_w2 + (bn0b + 16*q)*528 + bk);
                mma16816(acc2[0][2*q],   a0, b[0], b[1]);
                mma16816(acc2[1][2*q],   a1, b[0], b[1]);
                mma16816(acc2[0][2*q+1], a0, b[2], b[3]);
                mma16816(acc2[1][2*q+1], a1, b[2], b[3]);
            }
        }
        __syncthreads();   // H reads done; region becomes stage

        // ---- stage + coalesced store ----
        #pragma unroll
        for (int mb = 0; mb < 2; mb++) {
            const int R0 = 32*r + 16*mb + g;
            #pragma unroll
            for (int nb = 0; nb < 4; nb++) {
                const int C = 32*c + 8*nb + 2*tg;
                float* d = acc2[mb][nb];
                *(float2*)(stage + R0*130 + C)     = make_float2(d[0] + b2s[C], d[1] + b2s[C+1]);
                *(float2*)(stage + (R0+8)*130 + C) = make_float2(d[2] + b2s[C], d[3] + b2s[C+1]);
            }
        }
        if (tid < 128)
            stage[tid*130 + 128] = c128[tid] + c128[128+tid] + c128[256+tid] + c128[384+tid] + b2s[128];
        __syncthreads();
        {
            float* op = out + (size_t)base * OUT_CH;
            for (int i = tid; i < 128*OUT_CH; i += MTHREADS) {
                int rr = i / OUT_CH;
                int cc = i - rr*OUT_CH;
                op[i] = stage[rr*130 + cc];
            }
        }
        __syncthreads();
    }
}

// ================= launch =================
extern "C" void kernel_launch(void* const* d_in, const int* in_sizes, int n_in,
                              void* d_out, int out_size) {
    const float* xyz    = (const float*)d_in[0];
    const float* planes = (const float*)d_in[1];
    const float* lines  = (const float*)d_in[2];
    const float* w1     = (const float*)d_in[3];
    const float* b1     = (const float*)d_in[4];
    const float* w2     = (const float*)d_in[5];
    const float* b2     = (const float*)d_in[6];
    float* out = (float*)d_out;

    int sms = 148;
    cudaDeviceGetAttribute(&sms, cudaDevAttrMultiProcessorCount, 0);

    transpose_planes_kernel<<<3*GRID_R, 256>>>(planes);
    prep_weights_kernel<<<(256*144 + 255)/256, 256>>>(lines, w1, b1, w2);
    gather_kernel<<<N_TILES, GTHREADS, 8*16*304>>>(xyz);

    cudaFuncSetAttribute(mlp_kernel, cudaFuncAttributeMaxDynamicSharedMemorySize, SMEM_B);
    mlp_kernel<<<sms, MTHREADS, SMEM_B>>>(w2, b2, out);
}